// round 16
// baseline (speedup 1.0000x reference)
#include <cuda_runtime.h>
#include <cuda_fp16.h>
#include <cstdint>

// ---------------- problem constants ----------------
#define BATCH 32
#define CH    256
#define HH    56
#define WW    56
#define HO    28
#define WO    28
#define NPIX  (BATCH*HH*WW)      // 100352 valid output pixels
// flat-57 padded layout: col j of a padded row holds input col j-1
// (col 0 = left pad). Output f = h*57 + w taps input at f + r*57 + s;
// the w+s=57 overflow wraps into the next row's col 0 == required zero pad.
#define PROW  57                 // padded row width
#define PIMG  (58*57)            // 58 padded rows x 57 = 3306 pixels per image
#define MT_PER_IMG 25            // covers f in [0,3200) >= 3191 valid range

// conv tiling: CTA M=128 flat pixels x N=128 ch, K-chunk 32 per stage
#define NT        128
#define AROWS     130            // 128 pixels + 2 shift halo
#define RSTRB     80             // smem row stride bytes (40 halves)
#define RSTRH     40
#define AOFF      0
#define BOFF      (AROWS*RSTRB)                        // 10400
#define STAGE     ((BOFF + 384*RSTRB + 127) & ~127)    // 41216
#define DSMEM     (2*STAGE)                            // 82432 -> 2 CTAs/SM

// prep transpose smem row stride (halves)
#define TSTR      264
#define PREP_BLOCKS 512          // 4 jobs per block, 2048 jobs exactly

// ---------------- static scratch (zero-initialized) ----------------
__device__ __align__(128) __half g_xpad[(size_t)BATCH*PIMG*CH + 32768]; // [n][f][c]
__device__ __align__(128) __half g_wpack[9*256*256];                    // [rs][o][c]
__device__ __align__(128) __half g_ybuf[(size_t)NPIX*CH];               // NHWC conv out
__device__ float g_sum[256], g_sumsq[256];

// ---------------- helpers ----------------
__device__ __forceinline__ uint32_t su32(const void* p) {
    uint32_t a;
    asm("{.reg .u64 t; cvta.to.shared.u64 t, %1; cvt.u32.u64 %0, t;}" : "=r"(a) : "l"(p));
    return a;
}
__device__ __forceinline__ void cp16(uint32_t dst, const void* src) {
    asm volatile("cp.async.cg.shared.global [%0], [%1], 16;" :: "r"(dst), "l"(src));
}

// ---------------------------------------------------------------------------
// Kernel 1 (fused prep, persistent): 512 blocks x 512 threads, 4 jobs each.
//   job <  1792: x-pack (h = job%56, n = job/56): NCHW fp32 ->
//                flat-57 padded [n][(h+1)*57+(w+1)][c] fp16 (conflict-free)
//   job >= 1792: w-pack block wb = job-1792: sign(W) fp16 [rs][o][c]
// ---------------------------------------------------------------------------
__global__ __launch_bounds__(512) void prep_kernel(const float* __restrict__ x,
                                                   const float* __restrict__ W)
{
    __shared__ __half sm[56][TSTR];          // 29568 B
    const int tid = threadIdx.x;

    #pragma unroll 1
    for (int i = 0; i < 4; i++) {
        const int job = blockIdx.x + i * PREP_BLOCKS;

        if (job >= 1792) {                 // ---- weight pack path ----
            const int wb = job - 1792;                 // 0..255
            if (wb == 0 && tid < 256) { g_sum[tid] = 0.f; g_sumsq[tid] = 0.f; }
            #pragma unroll
            for (int j = 0; j < 4; j++) {
                int idx = wb * 2304 + j * 512 + tid;   // < 589824
                int c  = idx & 255;
                int o  = (idx >> 8) & 255;
                int rs = idx >> 16;
                int r  = rs / 3;
                int s  = rs - 3 * r;
                float v = W[(((size_t)o * 256 + c) * 3 + r) * 3 + s];
                float sv = (v > 0.f) ? 1.f : ((v < 0.f) ? -1.f : 0.f);
                g_wpack[idx] = __float2half(sv);
            }
            if (tid < 256) {
                int idx = wb * 2304 + 2048 + tid;
                int c  = idx & 255;
                int o  = (idx >> 8) & 255;
                int rs = idx >> 16;
                int r  = rs / 3;
                int s  = rs - 3 * r;
                float v = W[(((size_t)o * 256 + c) * 3 + r) * 3 + s];
                float sv = (v > 0.f) ? 1.f : ((v < 0.f) ? -1.f : 0.f);
                g_wpack[idx] = __float2half(sv);
            }
            continue;
        }

        // ---- x pack path (conflict-free smem transpose) ----
        const int h = job % 56, n = job / 56;
        const int wi  = tid & 63;                 // pixel w
        const int gid = tid >> 6;                 // 0..7
        __syncthreads();                          // guard smem reuse across jobs
        if (wi < 56) {
            #pragma unroll 1
            for (int grp = 0; grp < 4; grp++) {
                const int cq8 = grp * 8 + gid;    // 8-channel group 0..31
                __half tmp[8];
                const float* src = x + (((size_t)n * 256 + cq8 * 8) * 56 + h) * 56 + wi;
                #pragma unroll
                for (int j = 0; j < 8; j++)
                    tmp[j] = __float2half(src[(size_t)j * 56 * 56]);
                *(uint4*)&sm[wi][cq8 * 8] = *(uint4*)tmp;
            }
        }
        __syncthreads();
        #pragma unroll 1
        for (int chunk = tid; chunk < 56 * 32; chunk += 512) {
            int w = chunk >> 5, cq = chunk & 31;
            uint4 v = *(uint4*)&sm[w][cq * 8];
            *(uint4*)(g_xpad + ((size_t)n * PIMG + (h + 1) * PROW + (w + 1)) * CH + cq * 8)
                = v;
        }
    }
}

// ---------------------------------------------------------------------------
// Kernel 2: conv via mma.sync, flat-57 tiling, 2-deep cp.async ring,
// 2 CTAs/SM, fused masked BN stats.  (R15 keeper — at the HMMA rate floor)
// grid (2 ch-tiles, 25 f-tiles, 32 n) = 1600 CTAs, 256 thr (8 warps: 2m x 4n).
// ---------------------------------------------------------------------------
__global__ __launch_bounds__(256, 2) void conv_kernel()
{
    extern __shared__ __align__(128) char dsm[];
    __shared__ float sm_s1[128];
    __shared__ float sm_s2[128];

    const int n0  = blockIdx.x * NT;
    const int f0  = blockIdx.y * 128;          // flat output base
    const int nb  = blockIdx.z;
    const int tid = threadIdx.x;
    const int wid = tid >> 5, lane = tid & 31;
    const int g = lane >> 2, t = lane & 3;
    const int warp_m = wid & 1;                // 64 flat pixels each
    const int warp_n = wid >> 1;               // 32 channels each

    float acc[4][4][4];
    #pragma unroll
    for (int a = 0; a < 4; a++)
        #pragma unroll
        for (int b = 0; b < 4; b++)
            #pragma unroll
            for (int c = 0; c < 4; c++) acc[a][b][c] = 0.f;

    if (tid < 128) { sm_s1[tid] = 0.f; sm_s2[tid] = 0.f; }

    const __half* xp = g_xpad + (size_t)nb * PIMG * CH;

    auto load_stage = [&](int st) {
        char* sb = dsm + (st & 1) * STAGE;
        const int r = st >> 3, kb = st & 7;        // kb: 32-ch block
        const int pix0 = f0 + r * PROW;
        #pragma unroll 1
        for (int i = tid; i < AROWS * 4; i += 256) {
            int row = i >> 2, q = i & 3;
            cp16(su32(sb + AOFF + row * RSTRB + q * 16),
                 xp + (size_t)(pix0 + row) * CH + kb * 32 + q * 8);
        }
        const __half* wp = g_wpack + (size_t)(r * 3) * 65536 + (size_t)n0 * 256 + kb * 32;
        #pragma unroll 1
        for (int i = tid; i < 1536; i += 256) {
            int tap = i >> 9, rem = i & 511, nn = rem >> 2, q = rem & 3;
            cp16(su32(sb + BOFF + (tap * 128 + nn) * RSTRB + q * 16),
                 wp + (size_t)tap * 65536 + (size_t)nn * 256 + q * 8);
        }
        asm volatile("cp.async.commit_group;" ::: "memory");
    };

    auto compute = [&](int st) {
        const char* sb = dsm + (st & 1) * STAGE;
        const __half* sA = (const __half*)(sb + AOFF);
        const __half* sB = (const __half*)(sb + BOFF);
        #pragma unroll
        for (int s = 0; s < 3; s++) {
            #pragma unroll
            for (int kk = 0; kk < 2; kk++) {
                const int c0 = kk * 16 + 2 * t;
                uint32_t af[4][4];
                #pragma unroll
                for (int mt = 0; mt < 4; mt++) {
                    int row = warp_m * 64 + mt * 16 + g + s;
                    af[mt][0] = *(const uint32_t*)(sA + row * RSTRH + c0);
                    af[mt][1] = *(const uint32_t*)(sA + (row + 8) * RSTRH + c0);
                    af[mt][2] = *(const uint32_t*)(sA + row * RSTRH + c0 + 8);
                    af[mt][3] = *(const uint32_t*)(sA + (row + 8) * RSTRH + c0 + 8);
                }
                uint32_t bf[4][2];
                #pragma unroll
                for (int nt = 0; nt < 4; nt++) {
                    int nn = s * 128 + warp_n * 32 + nt * 8 + g;
                    bf[nt][0] = *(const uint32_t*)(sB + nn * RSTRH + c0);
                    bf[nt][1] = *(const uint32_t*)(sB + nn * RSTRH + c0 + 8);
                }
                #pragma unroll
                for (int mt = 0; mt < 4; mt++) {
                    #pragma unroll
                    for (int nt = 0; nt < 4; nt++) {
                        float* cacc = acc[mt][nt];
                        asm volatile(
                          "mma.sync.aligned.m16n8k16.row.col.f32.f16.f16.f32 "
                          "{%0,%1,%2,%3}, {%4,%5,%6,%7}, {%8,%9}, {%0,%1,%2,%3};\n"
                          : "+f"(cacc[0]), "+f"(cacc[1]), "+f"(cacc[2]), "+f"(cacc[3])
                          : "r"(af[mt][0]), "r"(af[mt][1]), "r"(af[mt][2]), "r"(af[mt][3]),
                            "r"(bf[nt][0]), "r"(bf[nt][1]));
                    }
                }
            }
        }
    };

    load_stage(0);
    load_stage(1);
    #pragma unroll 1
    for (int st = 0; st < 24; st++) {
        if (st < 23)
            asm volatile("cp.async.wait_group 1;" ::: "memory");
        else
            asm volatile("cp.async.wait_group 0;" ::: "memory");
        __syncthreads();                 // stage st visible to all warps
        compute(st);
        if (st + 2 < 24) {
            __syncthreads();             // all warps done reading slot st
            load_stage(st + 2);
        }
    }

    // ---- epilogue: acc -> fp16 NHWC (masked) + fused masked BN stats ----
    float s1[4][2], s2[4][2];
    #pragma unroll
    for (int nt = 0; nt < 4; nt++) { s1[nt][0]=s1[nt][1]=s2[nt][0]=s2[nt][1]=0.f; }

    #pragma unroll
    for (int mt = 0; mt < 4; mt++) {
        const int m0 = warp_m * 64 + mt * 16 + g;
        const int fA = f0 + m0;                 // rows g (regs 0,1)
        const int fB = fA + 8;                  // rows g+8 (regs 2,3)
        // exact floor(f/57) for f < 3200: (f*4600)>>18
        const int hA = (fA * 4600) >> 18, wA = fA - hA * PROW;
        const int hB = (fB * 4600) >> 18, wB = fB - hB * PROW;
        const bool vA = (wA < 56) && (hA < 56);
        const bool vB = (wB < 56) && (hB < 56);
        __half* pA = g_ybuf + ((size_t)((nb * HH + hA) * WW + wA)) * CH;
        __half* pB = g_ybuf + ((size_t)((nb * HH + hB) * WW + wB)) * CH;
        #pragma unroll
        for (int nt = 0; nt < 4; nt++) {
            const int ch0 = n0 + warp_n * 32 + nt * 8 + 2 * t;
            float f0v = acc[mt][nt][0], f1v = acc[mt][nt][1];
            float f2v = acc[mt][nt][2], f3v = acc[mt][nt][3];
            if (vA) {
                *(__half2*)(pA + ch0) = __floats2half2_rn(f0v, f1v);
                s1[nt][0] += f0v;  s2[nt][0] += f0v * f0v;
                s1[nt][1] += f1v;  s2[nt][1] += f1v * f1v;
            }
            if (vB) {
                *(__half2*)(pB + ch0) = __floats2half2_rn(f2v, f3v);
                s1[nt][0] += f2v;  s2[nt][0] += f2v * f2v;
                s1[nt][1] += f3v;  s2[nt][1] += f3v * f3v;
            }
        }
    }
    #pragma unroll
    for (int nt = 0; nt < 4; nt++) {
        #pragma unroll
        for (int p = 0; p < 2; p++) {
            #pragma unroll
            for (int m = 4; m < 32; m <<= 1) {
                s1[nt][p] += __shfl_xor_sync(0xffffffffu, s1[nt][p], m);
                s2[nt][p] += __shfl_xor_sync(0xffffffffu, s2[nt][p], m);
            }
        }
    }
    __syncthreads();
    if (g == 0) {
        #pragma unroll
        for (int nt = 0; nt < 4; nt++) {
            #pragma unroll
            for (int p = 0; p < 2; p++) {
                int chl = warp_n * 32 + nt * 8 + 2 * t + p;
                atomicAdd(&sm_s1[chl], s1[nt][p]);
                atomicAdd(&sm_s2[chl], s2[nt][p]);
            }
        }
    }
    __syncthreads();
    if (tid < 128) {
        atomicAdd(&g_sum[n0 + tid],   sm_s1[tid]);
        atomicAdd(&g_sumsq[n0 + tid], sm_s2[tid]);
    }
}

// ---------------------------------------------------------------------------
// Kernel 3: BN finalize + normalize + ReLU + 2x2 maxpool, -> NCHW fp32.
// grid (28 ho, 32 n, 2 ch-halves), 128 threads (16 blocks/SM -> ONE wave).
// c2 = tid&63 (channel pair within half), p = tid>>6 (wo parity).
// ---------------------------------------------------------------------------
__global__ __launch_bounds__(128) void pool_kernel(float* __restrict__ out,
                                                   const float* __restrict__ gamma,
                                                   const float* __restrict__ beta)
{
    __shared__ float sm[128 * WO];
    const int ho = blockIdx.x;
    const int n  = blockIdx.y;
    const int z  = blockIdx.z;              // channel half
    const int c2 = threadIdx.x & 63;        // pair within half
    const int p  = threadIdx.x >> 6;        // 0..1

    const float inv = 1.f / (float)NPIX;
    const int ca = z * 128 + 2 * c2, cb = ca + 1;
    float mA = g_sum[ca] * inv, vA = g_sumsq[ca] * inv - mA * mA;
    float scA = gamma[ca] * rsqrtf(vA + 1e-5f);
    float shA = beta[ca] - mA * scA;
    float mB = g_sum[cb] * inv, vB = g_sumsq[cb] * inv - mB * mB;
    float scB = gamma[cb] * rsqrtf(vB + 1e-5f);
    float shB = beta[cb] - mB * scB;

    const __half2* b0 = (const __half2*)(g_ybuf
                        + ((size_t)(n * HH + 2 * ho) * WW) * CH) + z * 64 + c2;
    const __half2* b1 = b0 + (size_t)WW * (CH / 2);

    #pragma unroll
    for (int k = 0; k < 14; k++) {
        const int wo = 2 * k + p;
        float2 a0 = __half22float2(b0[(size_t)(2 * wo)     * (CH / 2)]);
        float2 a1 = __half22float2(b0[(size_t)(2 * wo + 1) * (CH / 2)]);
        float2 a2 = __half22float2(b1[(size_t)(2 * wo)     * (CH / 2)]);
        float2 a3 = __half22float2(b1[(size_t)(2 * wo + 1) * (CH / 2)]);
        float q0 = fmaxf(a0.x * scA + shA, 0.f), q1 = fmaxf(a1.x * scA + shA, 0.f);
        float q2 = fmaxf(a2.x * scA + shA, 0.f), q3 = fmaxf(a3.x * scA + shA, 0.f);
        sm[(2 * c2) * WO + wo] = fmaxf(fmaxf(q0, q1), fmaxf(q2, q3));
        float r0 = fmaxf(a0.y * scB + shB, 0.f), r1 = fmaxf(a1.y * scB + shB, 0.f);
        float r2 = fmaxf(a2.y * scB + shB, 0.f), r3 = fmaxf(a3.y * scB + shB, 0.f);
        sm[(2 * c2 + 1) * WO + wo] = fmaxf(fmaxf(r0, r1), fmaxf(r2, r3));
    }
    __syncthreads();
    for (int i = threadIdx.x; i < 128 * WO; i += 128) {
        int cc = i / WO, wo = i % WO;
        out[(((size_t)n * CH + z * 128 + cc) * HO + ho) * WO + wo] = sm[i];
    }
}

// ---------------------------------------------------------------------------
extern "C" void kernel_launch(void* const* d_in, const int* in_sizes, int n_in,
                              void* d_out, int out_size)
{
    const float* x     = (const float*)d_in[0];
    const float* W     = (const float*)d_in[1];
    const float* gamma = (const float*)d_in[2];
    const float* beta  = (const float*)d_in[3];
    float* out = (float*)d_out;

    prep_kernel<<<PREP_BLOCKS, 512>>>(x, W);

    cudaFuncSetAttribute(conv_kernel, cudaFuncAttributeMaxDynamicSharedMemorySize, DSMEM);
    conv_kernel<<<dim3(2, MT_PER_IMG, BATCH), 256, DSMEM>>>();

    pool_kernel<<<dim3(HO, BATCH, 2), 128>>>(out, gamma, beta);
}

// round 17
// speedup vs baseline: 1.0587x; 1.0587x over previous
#include <cuda_runtime.h>
#include <cuda_fp16.h>
#include <cstdint>

// ---------------- problem constants ----------------
#define BATCH 32
#define CH    256
#define HH    56
#define WW    56
#define HO    28
#define WO    28
#define NPIX  (BATCH*HH*WW)      // 100352 valid output pixels
// flat-57 padded layout: col j of a padded row holds input col j-1
// (col 0 = left pad). Output f = h*57 + w taps input at f + r*57 + s;
// the w+s=57 overflow wraps into the next row's col 0 == required zero pad.
#define PROW  57                 // padded row width
#define PIMG  (58*57)            // 58 padded rows x 57 = 3306 pixels per image
#define MT_PER_IMG 25            // covers f in [0,3200) >= 3191 valid range

// conv tiling: CTA M=128 flat pixels x N=128 ch, K-chunk 32 per stage
#define NT        128
#define AROWS     130            // 128 pixels + 2 shift halo
#define RSTRB     80             // smem row stride bytes (40 halves)
#define RSTRH     40
#define AOFF      0
#define BOFF      (AROWS*RSTRB)                        // 10400
#define STAGE     ((BOFF + 384*RSTRB + 127) & ~127)    // 41216
#define DSMEM     (2*STAGE)                            // 82432 -> 2 CTAs/SM

// prep transpose smem row stride (halves)
#define TSTR      264

// ---------------- static scratch (zero-initialized) ----------------
// slack covers masked-tile halo over-reads past the last image
__device__ __align__(128) __half g_xpad[(size_t)BATCH*PIMG*CH + 32768]; // [n][f][c]
__device__ __align__(128) __half g_wpack[9*256*256];                    // [rs][o][c]
__device__ __align__(128) __half g_ybuf[(size_t)NPIX*CH];               // NHWC conv out
__device__ float g_sum[256], g_sumsq[256];

// ---------------- helpers ----------------
__device__ __forceinline__ uint32_t su32(const void* p) {
    uint32_t a;
    asm("{.reg .u64 t; cvta.to.shared.u64 t, %1; cvt.u32.u64 %0, t;}" : "=r"(a) : "l"(p));
    return a;
}
__device__ __forceinline__ void cp16(uint32_t dst, const void* src) {
    asm volatile("cp.async.cg.shared.global [%0], [%1], 16;" :: "r"(dst), "l"(src));
}

// ---------------------------------------------------------------------------
// Kernel 1 (fused prep, 512 threads): grid (64, 32).
//   bx <  56: transpose-pack x NCHW fp32 -> flat-57 padded [n][(h+1)*57+(w+1)][c]
//   bx >= 56: pack weights -> sign fp16 [rs][o][c]
// ---------------------------------------------------------------------------
__global__ __launch_bounds__(512) void prep_kernel(const float* __restrict__ x,
                                                   const float* __restrict__ W)
{
    __shared__ __half sm[56][TSTR];          // 29568 B
    const int bx = blockIdx.x, by = blockIdx.y;
    const int tid = threadIdx.x;

    if (bx >= 56) {                       // ---- weight pack path ----
        const int wb = (bx - 56) * 32 + by;            // 0..255
        if (wb == 0 && tid < 256) { g_sum[tid] = 0.f; g_sumsq[tid] = 0.f; }
        #pragma unroll
        for (int j = 0; j < 4; j++) {
            int idx = wb * 2304 + j * 512 + tid;       // < 589824
            int c  = idx & 255;
            int o  = (idx >> 8) & 255;
            int rs = idx >> 16;
            int r  = rs / 3;
            int s  = rs - 3 * r;
            float v = W[(((size_t)o * 256 + c) * 3 + r) * 3 + s];
            float sv = (v > 0.f) ? 1.f : ((v < 0.f) ? -1.f : 0.f);
            g_wpack[idx] = __float2half(sv);
        }
        if (tid < 256) {
            int idx = wb * 2304 + 2048 + tid;
            int c  = idx & 255;
            int o  = (idx >> 8) & 255;
            int rs = idx >> 16;
            int r  = rs / 3;
            int s  = rs - 3 * r;
            float v = W[(((size_t)o * 256 + c) * 3 + r) * 3 + s];
            float sv = (v > 0.f) ? 1.f : ((v < 0.f) ? -1.f : 0.f);
            g_wpack[idx] = __float2half(sv);
        }
        return;
    }

    // ---- x pack path (conflict-free smem transpose) ----
    const int h = bx, n = by;
    const int wi  = tid & 63;                 // pixel w
    const int gid = tid >> 6;                 // 0..7
    if (wi < 56) {
        #pragma unroll 1
        for (int grp = 0; grp < 4; grp++) {
            const int cq8 = grp * 8 + gid;    // 8-channel group 0..31
            __half tmp[8];
            const float* src = x + (((size_t)n * 256 + cq8 * 8) * 56 + h) * 56 + wi;
            #pragma unroll
            for (int j = 0; j < 8; j++)
                tmp[j] = __float2half(src[(size_t)j * 56 * 56]);
            *(uint4*)&sm[wi][cq8 * 8] = *(uint4*)tmp;
        }
    }
    __syncthreads();
    #pragma unroll 1
    for (int chunk = tid; chunk < 56 * 32; chunk += 512) {
        int w = chunk >> 5, cq = chunk & 31;
        uint4 v = *(uint4*)&sm[w][cq * 8];
        *(uint4*)(g_xpad + ((size_t)n * PIMG + (h + 1) * PROW + (w + 1)) * CH + cq * 8)
            = v;
    }
}

// ---------------------------------------------------------------------------
// Kernel 2: conv via mma.sync, flat-57 tiling, 2-deep cp.async ring,
// 2 CTAs/SM, fused masked BN stats.
// grid (2 ch-tiles, 25 f-tiles, 32 n) = 1600 CTAs, 256 thr (8 warps: 2m x 4n).
// 24 smem stages = 3 h-taps x 8 blocks of 32 in-ch.
// ---------------------------------------------------------------------------
__global__ __launch_bounds__(256, 2) void conv_kernel()
{
    extern __shared__ __align__(128) char dsm[];
    __shared__ float sm_s1[128];
    __shared__ float sm_s2[128];

    const int n0  = blockIdx.x * NT;
    const int f0  = blockIdx.y * 128;          // flat output base
    const int nb  = blockIdx.z;
    const int tid = threadIdx.x;
    const int wid = tid >> 5, lane = tid & 31;
    const int g = lane >> 2, t = lane & 3;
    const int warp_m = wid & 1;                // 64 flat pixels each
    const int warp_n = wid >> 1;               // 32 channels each

    float acc[4][4][4];
    #pragma unroll
    for (int a = 0; a < 4; a++)
        #pragma unroll
        for (int b = 0; b < 4; b++)
            #pragma unroll
            for (int c = 0; c < 4; c++) acc[a][b][c] = 0.f;

    if (tid < 128) { sm_s1[tid] = 0.f; sm_s2[tid] = 0.f; }

    const __half* xp = g_xpad + (size_t)nb * PIMG * CH;

    auto load_stage = [&](int st) {
        char* sb = dsm + (st & 1) * STAGE;
        const int r = st >> 3, kb = st & 7;        // kb: 32-ch block
        const int pix0 = f0 + r * PROW;
        #pragma unroll 1
        for (int i = tid; i < AROWS * 4; i += 256) {
            int row = i >> 2, q = i & 3;
            cp16(su32(sb + AOFF + row * RSTRB + q * 16),
                 xp + (size_t)(pix0 + row) * CH + kb * 32 + q * 8);
        }
        const __half* wp = g_wpack + (size_t)(r * 3) * 65536 + (size_t)n0 * 256 + kb * 32;
        #pragma unroll 1
        for (int i = tid; i < 1536; i += 256) {
            int tap = i >> 9, rem = i & 511, nn = rem >> 2, q = rem & 3;
            cp16(su32(sb + BOFF + (tap * 128 + nn) * RSTRB + q * 16),
                 wp + (size_t)tap * 65536 + (size_t)nn * 256 + q * 8);
        }
        asm volatile("cp.async.commit_group;" ::: "memory");
    };

    auto compute = [&](int st) {
        const char* sb = dsm + (st & 1) * STAGE;
        const __half* sA = (const __half*)(sb + AOFF);
        const __half* sB = (const __half*)(sb + BOFF);
        #pragma unroll
        for (int s = 0; s < 3; s++) {
            #pragma unroll
            for (int kk = 0; kk < 2; kk++) {
                const int c0 = kk * 16 + 2 * t;
                uint32_t af[4][4];
                #pragma unroll
                for (int mt = 0; mt < 4; mt++) {
                    int row = warp_m * 64 + mt * 16 + g + s;
                    af[mt][0] = *(const uint32_t*)(sA + row * RSTRH + c0);
                    af[mt][1] = *(const uint32_t*)(sA + (row + 8) * RSTRH + c0);
                    af[mt][2] = *(const uint32_t*)(sA + row * RSTRH + c0 + 8);
                    af[mt][3] = *(const uint32_t*)(sA + (row + 8) * RSTRH + c0 + 8);
                }
                uint32_t bf[4][2];
                #pragma unroll
                for (int nt = 0; nt < 4; nt++) {
                    int nn = s * 128 + warp_n * 32 + nt * 8 + g;
                    bf[nt][0] = *(const uint32_t*)(sB + nn * RSTRH + c0);
                    bf[nt][1] = *(const uint32_t*)(sB + nn * RSTRH + c0 + 8);
                }
                #pragma unroll
                for (int mt = 0; mt < 4; mt++) {
                    #pragma unroll
                    for (int nt = 0; nt < 4; nt++) {
                        float* cacc = acc[mt][nt];
                        asm volatile(
                          "mma.sync.aligned.m16n8k16.row.col.f32.f16.f16.f32 "
                          "{%0,%1,%2,%3}, {%4,%5,%6,%7}, {%8,%9}, {%0,%1,%2,%3};\n"
                          : "+f"(cacc[0]), "+f"(cacc[1]), "+f"(cacc[2]), "+f"(cacc[3])
                          : "r"(af[mt][0]), "r"(af[mt][1]), "r"(af[mt][2]), "r"(af[mt][3]),
                            "r"(bf[nt][0]), "r"(bf[nt][1]));
                    }
                }
            }
        }
    };

    load_stage(0);
    load_stage(1);
    #pragma unroll 1
    for (int st = 0; st < 24; st++) {
        if (st < 23)
            asm volatile("cp.async.wait_group 1;" ::: "memory");
        else
            asm volatile("cp.async.wait_group 0;" ::: "memory");
        __syncthreads();                 // stage st visible to all warps
        compute(st);
        if (st + 2 < 24) {
            __syncthreads();             // all warps done reading slot st
            load_stage(st + 2);
        }
    }

    // ---- epilogue: acc -> fp16 NHWC (masked) + fused masked BN stats ----
    float s1[4][2], s2[4][2];
    #pragma unroll
    for (int nt = 0; nt < 4; nt++) { s1[nt][0]=s1[nt][1]=s2[nt][0]=s2[nt][1]=0.f; }

    #pragma unroll
    for (int mt = 0; mt < 4; mt++) {
        const int m0 = warp_m * 64 + mt * 16 + g;
        const int fA = f0 + m0;                 // rows g (regs 0,1)
        const int fB = fA + 8;                  // rows g+8 (regs 2,3)
        // exact floor(f/57) for f < 3200: (f*4600)>>18
        const int hA = (fA * 4600) >> 18, wA = fA - hA * PROW;
        const int hB = (fB * 4600) >> 18, wB = fB - hB * PROW;
        const bool vA = (wA < 56) && (hA < 56);
        const bool vB = (wB < 56) && (hB < 56);
        __half* pA = g_ybuf + ((size_t)((nb * HH + hA) * WW + wA)) * CH;
        __half* pB = g_ybuf + ((size_t)((nb * HH + hB) * WW + wB)) * CH;
        #pragma unroll
        for (int nt = 0; nt < 4; nt++) {
            const int ch0 = n0 + warp_n * 32 + nt * 8 + 2 * t;
            float f0v = acc[mt][nt][0], f1v = acc[mt][nt][1];
            float f2v = acc[mt][nt][2], f3v = acc[mt][nt][3];
            if (vA) {
                *(__half2*)(pA + ch0) = __floats2half2_rn(f0v, f1v);
                s1[nt][0] += f0v;  s2[nt][0] += f0v * f0v;
                s1[nt][1] += f1v;  s2[nt][1] += f1v * f1v;
            }
            if (vB) {
                *(__half2*)(pB + ch0) = __floats2half2_rn(f2v, f3v);
                s1[nt][0] += f2v;  s2[nt][0] += f2v * f2v;
                s1[nt][1] += f3v;  s2[nt][1] += f3v * f3v;
            }
        }
    }
    #pragma unroll
    for (int nt = 0; nt < 4; nt++) {
        #pragma unroll
        for (int p = 0; p < 2; p++) {
            #pragma unroll
            for (int m = 4; m < 32; m <<= 1) {
                s1[nt][p] += __shfl_xor_sync(0xffffffffu, s1[nt][p], m);
                s2[nt][p] += __shfl_xor_sync(0xffffffffu, s2[nt][p], m);
            }
        }
    }
    __syncthreads();
    if (g == 0) {
        #pragma unroll
        for (int nt = 0; nt < 4; nt++) {
            #pragma unroll
            for (int p = 0; p < 2; p++) {
                int chl = warp_n * 32 + nt * 8 + 2 * t + p;
                atomicAdd(&sm_s1[chl], s1[nt][p]);
                atomicAdd(&sm_s2[chl], s2[nt][p]);
            }
        }
    }
    __syncthreads();
    if (tid < 128) {
        atomicAdd(&g_sum[n0 + tid],   sm_s1[tid]);
        atomicAdd(&g_sumsq[n0 + tid], sm_s2[tid]);
    }
}

// ---------------------------------------------------------------------------
// Kernel 3: BN finalize + normalize + ReLU + 2x2 maxpool, -> NCHW fp32.
// grid (28 ho, 32 n, 2 ch-halves), 256 threads. 14KB smem/block.
// ---------------------------------------------------------------------------
__global__ __launch_bounds__(256) void pool_kernel(float* __restrict__ out,
                                                   const float* __restrict__ gamma,
                                                   const float* __restrict__ beta)
{
    __shared__ float sm[128 * WO];
    const int ho = blockIdx.x;
    const int n  = blockIdx.y;
    const int z  = blockIdx.z;              // channel half
    const int c2 = threadIdx.x & 63;        // pair within half
    const int p  = threadIdx.x >> 6;        // 0..3

    const float inv = 1.f / (float)NPIX;
    const int ca = z * 128 + 2 * c2, cb = ca + 1;
    float mA = g_sum[ca] * inv, vA = g_sumsq[ca] * inv - mA * mA;
    float scA = gamma[ca] * rsqrtf(vA + 1e-5f);
    float shA = beta[ca] - mA * scA;
    float mB = g_sum[cb] * inv, vB = g_sumsq[cb] * inv - mB * mB;
    float scB = gamma[cb] * rsqrtf(vB + 1e-5f);
    float shB = beta[cb] - mB * scB;

    const __half2* b0 = (const __half2*)(g_ybuf
                        + ((size_t)(n * HH + 2 * ho) * WW) * CH) + z * 64 + c2;
    const __half2* b1 = b0 + (size_t)WW * (CH / 2);

    #pragma unroll
    for (int k = 0; k < 7; k++) {
        const int wo = 4 * k + p;
        float2 a0 = __half22float2(b0[(size_t)(2 * wo)     * (CH / 2)]);
        float2 a1 = __half22float2(b0[(size_t)(2 * wo + 1) * (CH / 2)]);
        float2 a2 = __half22float2(b1[(size_t)(2 * wo)     * (CH / 2)]);
        float2 a3 = __half22float2(b1[(size_t)(2 * wo + 1) * (CH / 2)]);
        float q0 = fmaxf(a0.x * scA + shA, 0.f), q1 = fmaxf(a1.x * scA + shA, 0.f);
        float q2 = fmaxf(a2.x * scA + shA, 0.f), q3 = fmaxf(a3.x * scA + shA, 0.f);
        sm[(2 * c2) * WO + wo] = fmaxf(fmaxf(q0, q1), fmaxf(q2, q3));
        float r0 = fmaxf(a0.y * scB + shB, 0.f), r1 = fmaxf(a1.y * scB + shB, 0.f);
        float r2 = fmaxf(a2.y * scB + shB, 0.f), r3 = fmaxf(a3.y * scB + shB, 0.f);
        sm[(2 * c2 + 1) * WO + wo] = fmaxf(fmaxf(r0, r1), fmaxf(r2, r3));
    }
    __syncthreads();
    for (int i = threadIdx.x; i < 128 * WO; i += 256) {
        int cc = i / WO, wo = i % WO;
        out[(((size_t)n * CH + z * 128 + cc) * HO + ho) * WO + wo] = sm[i];
    }
}

// ---------------------------------------------------------------------------
extern "C" void kernel_launch(void* const* d_in, const int* in_sizes, int n_in,
                              void* d_out, int out_size)
{
    const float* x     = (const float*)d_in[0];
    const float* W     = (const float*)d_in[1];
    const float* gamma = (const float*)d_in[2];
    const float* beta  = (const float*)d_in[3];
    float* out = (float*)d_out;

    prep_kernel<<<dim3(64, BATCH), 512>>>(x, W);

    cudaFuncSetAttribute(conv_kernel, cudaFuncAttributeMaxDynamicSharedMemorySize, DSMEM);
    conv_kernel<<<dim3(2, MT_PER_IMG, BATCH), 256, DSMEM>>>();

    pool_kernel<<<dim3(HO, BATCH, 2), 256>>>(out, gamma, beta);
}